// round 1
// baseline (speedup 1.0000x reference)
#include <cuda_runtime.h>
#include <math.h>

#define BATCH 8
#define SEQ   2048
#define DIM   512
#define NCHUNK 16   // i-chunks for column stats

static const float LN_EPS_F = 1e-5f;
static const float EPS_F    = 1e-8f;

// ---------------- scratch (static device globals; no allocation) ----------------
__device__ float g_xn  [(size_t)BATCH * SEQ * DIM];
__device__ float g_cn  [(size_t)BATCH * SEQ * DIM];
__device__ float g_q   [(size_t)BATCH * SEQ * DIM];
__device__ float g_k   [(size_t)BATCH * SEQ * DIM];
__device__ float g_v   [(size_t)BATCH * SEQ * DIM];
__device__ float g_dots[(size_t)BATCH * SEQ * SEQ];
__device__ float g_pm  [BATCH * NCHUNK * SEQ];
__device__ float g_ps  [BATCH * NCHUNK * SEQ];
__device__ float g_cm  [BATCH * SEQ];
__device__ float g_csi [BATCH * SEQ];
__device__ float g_rinv[BATCH * SEQ];

// ---------------- LayerNorm: one block per row of 512 ----------------
__global__ void __launch_bounds__(128) ln_kernel(const float* __restrict__ x,
                                                 const float* __restrict__ g,
                                                 const float* __restrict__ b,
                                                 float* __restrict__ y) {
    int row = blockIdx.x;
    int t = threadIdx.x;  // 128 threads * 4 floats = 512
    const float4* xr = (const float4*)(x + (size_t)row * DIM);
    float4 v = xr[t];
    float s  = v.x + v.y + v.z + v.w;
    float ss = v.x*v.x + v.y*v.y + v.z*v.z + v.w*v.w;
    __shared__ float sh[8];
    #pragma unroll
    for (int o = 16; o > 0; o >>= 1) {
        s  += __shfl_down_sync(0xffffffffu, s, o);
        ss += __shfl_down_sync(0xffffffffu, ss, o);
    }
    if ((t & 31) == 0) { sh[t >> 5] = s; sh[4 + (t >> 5)] = ss; }
    __syncthreads();
    float fs  = sh[0] + sh[1] + sh[2] + sh[3];
    float fss = sh[4] + sh[5] + sh[6] + sh[7];
    float mu  = fs * (1.0f / DIM);
    float var = fss * (1.0f / DIM) - mu * mu;
    float rstd = rsqrtf(var + LN_EPS_F);
    float4 gv = ((const float4*)g)[t];
    float4 bv = ((const float4*)b)[t];
    float4 o;
    o.x = (v.x - mu) * rstd * gv.x + bv.x;
    o.y = (v.y - mu) * rstd * gv.y + bv.y;
    o.z = (v.z - mu) * rstd * gv.z + bv.z;
    o.w = (v.w - mu) * rstd * gv.w + bv.w;
    ((float4*)(y + (size_t)row * DIM))[t] = o;
}

// ---------------- generic 128x128x8 SGEMM, 256 threads, 8x8 per thread ----------------
// TB=false: C[M,N] = alpha * A[M,K] @ B[K,N]   (+bias[N]) (*rowscale[z*M+row])
// TB=true : C[M,N] = alpha * A[M,K] @ B[N,K]^T
// All dims assumed multiples of tile sizes (true for all calls here).
template <bool TB>
__global__ void __launch_bounds__(256) sgemm_kernel(
    const float* __restrict__ A, const float* __restrict__ B, float* __restrict__ C,
    int M, int N, int K,
    size_t sA, size_t sB, size_t sC,
    float alpha,
    const float* __restrict__ bias,
    const float* __restrict__ rowscale)
{
    int z = blockIdx.z;
    A += (size_t)z * sA;
    B += (size_t)z * sB;
    C += (size_t)z * sC;
    int bm = blockIdx.y * 128;
    int bn = blockIdx.x * 128;

    __shared__ float As[8][128];
    __shared__ float Bs[8][128];

    int t = threadIdx.x;
    int aRow = t >> 1, aCol = (t & 1) * 4;        // A tile: 128 rows x 8 k
    int bRow = t >> 5, bCol = (t & 31) * 4;       // B tile (NN): 8 k x 128 cols
    int ty = t >> 4, tx = t & 15;
    int m0 = ty * 8, n0 = tx * 8;

    float acc[8][8];
    #pragma unroll
    for (int i = 0; i < 8; i++)
        #pragma unroll
        for (int j = 0; j < 8; j++) acc[i][j] = 0.0f;

    for (int k0 = 0; k0 < K; k0 += 8) {
        float4 av = *(const float4*)(A + (size_t)(bm + aRow) * K + k0 + aCol);
        As[aCol + 0][aRow] = av.x;
        As[aCol + 1][aRow] = av.y;
        As[aCol + 2][aRow] = av.z;
        As[aCol + 3][aRow] = av.w;
        if (TB) {
            float4 bvv = *(const float4*)(B + (size_t)(bn + aRow) * K + k0 + aCol);
            Bs[aCol + 0][aRow] = bvv.x;
            Bs[aCol + 1][aRow] = bvv.y;
            Bs[aCol + 2][aRow] = bvv.z;
            Bs[aCol + 3][aRow] = bvv.w;
        } else {
            float4 bvv = *(const float4*)(B + (size_t)(k0 + bRow) * N + bn + bCol);
            *(float4*)&Bs[bRow][bCol] = bvv;
        }
        __syncthreads();
        #pragma unroll
        for (int kk = 0; kk < 8; kk++) {
            float a[8], bb[8];
            float4 a0 = *(const float4*)&As[kk][m0];
            float4 a1 = *(const float4*)&As[kk][m0 + 4];
            float4 b0 = *(const float4*)&Bs[kk][n0];
            float4 b1 = *(const float4*)&Bs[kk][n0 + 4];
            a[0]=a0.x; a[1]=a0.y; a[2]=a0.z; a[3]=a0.w;
            a[4]=a1.x; a[5]=a1.y; a[6]=a1.z; a[7]=a1.w;
            bb[0]=b0.x; bb[1]=b0.y; bb[2]=b0.z; bb[3]=b0.w;
            bb[4]=b1.x; bb[5]=b1.y; bb[6]=b1.z; bb[7]=b1.w;
            #pragma unroll
            for (int i = 0; i < 8; i++)
                #pragma unroll
                for (int j = 0; j < 8; j++)
                    acc[i][j] = fmaf(a[i], bb[j], acc[i][j]);
        }
        __syncthreads();
    }

    #pragma unroll
    for (int i = 0; i < 8; i++) {
        int row = bm + m0 + i;
        float rs = rowscale ? rowscale[(size_t)z * M + row] : 1.0f;
        #pragma unroll
        for (int j = 0; j < 8; j += 4) {
            float4 o;
            o.x = acc[i][j + 0] * alpha;
            o.y = acc[i][j + 1] * alpha;
            o.z = acc[i][j + 2] * alpha;
            o.w = acc[i][j + 3] * alpha;
            if (bias) {
                o.x += bias[bn + n0 + j + 0];
                o.y += bias[bn + n0 + j + 1];
                o.z += bias[bn + n0 + j + 2];
                o.w += bias[bn + n0 + j + 3];
            }
            o.x *= rs; o.y *= rs; o.z *= rs; o.w *= rs;
            *(float4*)(C + (size_t)row * N + bn + n0 + j) = o;
        }
    }
}

// ---------------- column stats stage 1: per (b, chunk, j) partial max & sumexp ----------------
__global__ void __launch_bounds__(128) colstats1_kernel() {
    int j = blockIdx.x * 128 + threadIdx.x;
    int c = blockIdx.y;
    int z = blockIdx.z;
    const float* p = g_dots + ((size_t)z * SEQ + (size_t)c * (SEQ / NCHUNK)) * SEQ + j;
    float m = -1e30f;
    #pragma unroll 4
    for (int r = 0; r < SEQ / NCHUNK; r++)
        m = fmaxf(m, p[(size_t)r * SEQ]);
    float s = 0.0f;
    #pragma unroll 4
    for (int r = 0; r < SEQ / NCHUNK; r++)
        s += __expf(p[(size_t)r * SEQ] - m);
    g_pm[((size_t)z * NCHUNK + c) * SEQ + j] = m;
    g_ps[((size_t)z * NCHUNK + c) * SEQ + j] = s;
}

// ---------------- column stats stage 2: combine chunks -> colmax, 1/colsum ----------------
__global__ void __launch_bounds__(256) colstats2_kernel() {
    int j = blockIdx.x * 256 + threadIdx.x;
    int z = blockIdx.y;
    float m = -1e30f;
    #pragma unroll
    for (int c = 0; c < NCHUNK; c++)
        m = fmaxf(m, g_pm[((size_t)z * NCHUNK + c) * SEQ + j]);
    float s = 0.0f;
    #pragma unroll
    for (int c = 0; c < NCHUNK; c++)
        s += g_ps[((size_t)z * NCHUNK + c) * SEQ + j] *
             __expf(g_pm[((size_t)z * NCHUNK + c) * SEQ + j] - m);
    g_cm [(size_t)z * SEQ + j] = m;
    g_csi[(size_t)z * SEQ + j] = 1.0f / s;
}

// ---------------- row pass: overwrite dots with Araw = softmax+EPS, compute 1/(rowsum+EPS) ----------------
__global__ void __launch_bounds__(256) rowpass_kernel() {
    int i = blockIdx.x;
    int z = blockIdx.y;
    int t = threadIdx.x;
    float* row = g_dots + ((size_t)z * SEQ + i) * SEQ;
    const float* cm = g_cm  + (size_t)z * SEQ;
    const float* ci = g_csi + (size_t)z * SEQ;
    float acc = 0.0f;
    #pragma unroll 2
    for (int j = t; j < SEQ; j += 256) {
        float a = __expf(row[j] - cm[j]) * ci[j] + EPS_F;
        acc += a;
        row[j] = a;
    }
    __shared__ float sh[8];
    #pragma unroll
    for (int o = 16; o > 0; o >>= 1)
        acc += __shfl_down_sync(0xffffffffu, acc, o);
    if ((t & 31) == 0) sh[t >> 5] = acc;
    __syncthreads();
    if (t == 0) {
        float s = 0.0f;
        #pragma unroll
        for (int w = 0; w < 8; w++) s += sh[w];
        g_rinv[(size_t)z * SEQ + i] = 1.0f / (s + EPS_F);
    }
}

// ---------------- launch ----------------
extern "C" void kernel_launch(void* const* d_in, const int* in_sizes, int n_in,
                              void* d_out, int out_size) {
    const float* inputs  = (const float*)d_in[0];
    const float* context = (const float*)d_in[1];
    const float* gin  = (const float*)d_in[2];
    const float* bin  = (const float*)d_in[3];
    const float* gctx = (const float*)d_in[4];
    const float* bctx = (const float*)d_in[5];
    const float* Wq = (const float*)d_in[6];
    const float* bq = (const float*)d_in[7];
    const float* Wk = (const float*)d_in[8];
    const float* bk = (const float*)d_in[9];
    const float* Wv = (const float*)d_in[10];
    const float* bv = (const float*)d_in[11];
    float* out = (float*)d_out;

    float *xn, *cn, *q, *k, *v, *dots, *rinv;
    cudaGetSymbolAddress((void**)&xn,   g_xn);
    cudaGetSymbolAddress((void**)&cn,   g_cn);
    cudaGetSymbolAddress((void**)&q,    g_q);
    cudaGetSymbolAddress((void**)&k,    g_k);
    cudaGetSymbolAddress((void**)&v,    g_v);
    cudaGetSymbolAddress((void**)&dots, g_dots);
    cudaGetSymbolAddress((void**)&rinv, g_rinv);

    // LayerNorms
    ln_kernel<<<BATCH * SEQ, 128>>>(inputs,  gin,  bin,  xn);
    ln_kernel<<<BATCH * SEQ, 128>>>(context, gctx, bctx, cn);

    // QKV projections: M=16384, N=512, K=512 (batch folded into M; W shared)
    {
        dim3 grid(DIM / 128, (BATCH * SEQ) / 128, 1);
        sgemm_kernel<false><<<grid, 256>>>(xn, Wq, q, BATCH * SEQ, DIM, DIM,
                                           0, 0, 0, 1.0f, bq, nullptr);
        sgemm_kernel<false><<<grid, 256>>>(cn, Wk, k, BATCH * SEQ, DIM, DIM,
                                           0, 0, 0, 1.0f, bk, nullptr);
        sgemm_kernel<false><<<grid, 256>>>(cn, Wv, v, BATCH * SEQ, DIM, DIM,
                                           0, 0, 0, 1.0f, bv, nullptr);
    }

    // dots = q @ k^T * scale   (batched)
    {
        float scale = 1.0f / sqrtf((float)DIM);
        dim3 grid(SEQ / 128, SEQ / 128, BATCH);
        sgemm_kernel<true><<<grid, 256>>>(q, k, dots, SEQ, SEQ, DIM,
                                          (size_t)SEQ * DIM, (size_t)SEQ * DIM,
                                          (size_t)SEQ * SEQ, scale, nullptr, nullptr);
    }

    // column softmax stats (over i for each (b,j))
    colstats1_kernel<<<dim3(SEQ / 128, NCHUNK, BATCH), 128>>>();
    colstats2_kernel<<<dim3(SEQ / 256, BATCH), 256>>>();

    // rowpass: dots -> Araw = softmax+EPS, rinv = 1/(rowsum+EPS)
    rowpass_kernel<<<dim3(SEQ, BATCH), 256>>>();

    // updates = rinv[i] * (Araw @ v)   (batched)
    {
        dim3 grid(DIM / 128, SEQ / 128, BATCH);
        sgemm_kernel<false><<<grid, 256>>>(dots, v, out, SEQ, DIM, SEQ,
                                           (size_t)SEQ * SEQ, (size_t)SEQ * DIM,
                                           (size_t)SEQ * DIM, 1.0f, nullptr, rinv);
    }
}